// round 15
// baseline (speedup 1.0000x reference)
#include <cuda_runtime.h>
#include <cuda_fp16.h>

#define NROWS   16384
#define INC     512
#define NG      64
#define NF      24
#define NO      16
#define ACCC    3584
#define RT      16
#define NTHR    256
#define TILE_BYTES (ACCC * RT * 2)   // 114688: 2 blocks/SM (229376 <= 228KB)

typedef unsigned long long u64;

static __device__ __forceinline__ u64 pk2(float a, float b) {
    u64 r;
    asm("mov.b64 %0, {%1, %2};" : "=l"(r) : "f"(a), "f"(b));
    return r;
}
static __device__ __forceinline__ void up2(u64 v, float &a, float &b) {
    asm("mov.b64 {%0, %1}, %2;" : "=f"(a), "=f"(b) : "l"(v));
}
static __device__ __forceinline__ u64 fma2(u64 a, u64 b, u64 c) {
    u64 d;
    asm("fma.rn.f32x2 %0, %1, %2, %3;" : "=l"(d) : "l"(a), "l"(b), "l"(c));
    return d;
}
static __device__ __forceinline__ float tanhhw(float x) {
    float y;
    asm("tanh.approx.f32 %0, %1;" : "=f"(y) : "f"(x));
    return y;
}
static __device__ __forceinline__ float2 h2f(unsigned u) {
    __half2 h = reinterpret_cast<__half2&>(u);
    return __half22float2(h);
}

// fp16 tile [col][16 rows]: column = 32 B = 4 slots of 8 B (4 rows each).
// Slot s of column c lives at physical slot s ^ H2(c); H2 mixes col bits
// 2..5 so random gathers, staging stores and the 16-col writeback all spread.
#define H2(c)  ((((c) >> 2) ^ ((c) >> 4)) & 3)

static __device__ __forceinline__ uint2* qp(uint2* tile, int c, int s) {
    return tile + c * 4 + (s ^ H2(c));
}

// Thread = (g, s): group g, row-quad s (rows 4s..4s+3), all 16 outputs.
// Two o-half passes (outputs 8h..8h+7); acc[r][j] = f32x2 over outputs
// (8h+2j, 8h+2j+1), row r. Depth-2 rolling weight prefetch (3 buffers).
static __device__ __forceinline__ void glayer(uint2* tile, int g, int s,
                                              const float* __restrict__ W,
                                              const float* __restrict__ bia,
                                              const int* __restrict__ idx,
                                              int colbase)
{
    int cols[NF];
    const int4* ip = reinterpret_cast<const int4*>(idx + g * NF);
    #pragma unroll
    for (int i = 0; i < NF / 4; i++) {
        int4 v = __ldg(&ip[i]);
        cols[4 * i + 0] = v.x; cols[4 * i + 1] = v.y;
        cols[4 * i + 2] = v.z; cols[4 * i + 3] = v.w;
    }
    const ulonglong2* wb = reinterpret_cast<const ulonglong2*>(W + (size_t)g * NF * NO);
    const float2*     b2 = reinterpret_cast<const float2*>(bia + g * NO);

    #pragma unroll
    for (int h = 0; h < 2; h++) {
        u64 acc[4][4];
        #pragma unroll
        for (int j = 0; j < 4; j++) {
            float2 bb = __ldg(&b2[4 * h + j]);
            u64 bv = pk2(bb.x, bb.y);
            acc[0][j] = bv; acc[1][j] = bv; acc[2][j] = bv; acc[3][j] = bv;
        }

        // depth-2 rolling prefetch of this half's 32B weight slice
        ulonglong2 wA[3], wB[3];
        wA[0] = __ldg(&wb[0 * 4 + 2 * h]); wB[0] = __ldg(&wb[0 * 4 + 2 * h + 1]);
        wA[1] = __ldg(&wb[1 * 4 + 2 * h]); wB[1] = __ldg(&wb[1 * 4 + 2 * h + 1]);

        #pragma unroll
        for (int f = 0; f < NF; f++) {
            if (f + 2 < NF) {
                wA[(f + 2) % 3] = __ldg(&wb[(f + 2) * 4 + 2 * h]);
                wB[(f + 2) % 3] = __ldg(&wb[(f + 2) * 4 + 2 * h + 1]);
            }
            uint2 a = *qp(tile, cols[f], s);
            float2 r01 = h2f(a.x), r23 = h2f(a.y);
            u64 d0 = pk2(r01.x, r01.x), d1 = pk2(r01.y, r01.y);
            u64 d2 = pk2(r23.x, r23.x), d3 = pk2(r23.y, r23.y);
            int bi = f % 3;
            u64 u0 = wA[bi].x, u1 = wA[bi].y, u2 = wB[bi].x, u3 = wB[bi].y;
            acc[0][0] = fma2(d0, u0, acc[0][0]); acc[0][1] = fma2(d0, u1, acc[0][1]);
            acc[0][2] = fma2(d0, u2, acc[0][2]); acc[0][3] = fma2(d0, u3, acc[0][3]);
            acc[1][0] = fma2(d1, u0, acc[1][0]); acc[1][1] = fma2(d1, u1, acc[1][1]);
            acc[1][2] = fma2(d1, u2, acc[1][2]); acc[1][3] = fma2(d1, u3, acc[1][3]);
            acc[2][0] = fma2(d2, u0, acc[2][0]); acc[2][1] = fma2(d2, u1, acc[2][1]);
            acc[2][2] = fma2(d2, u2, acc[2][2]); acc[2][3] = fma2(d2, u3, acc[2][3]);
            acc[3][0] = fma2(d3, u0, acc[3][0]); acc[3][1] = fma2(d3, u1, acc[3][1]);
            acc[3][2] = fma2(d3, u2, acc[3][2]); acc[3][3] = fma2(d3, u3, acc[3][3]);
        }

        // tanh + fp16 writeback for this o-half: 8 cols x 4 rows
        float v[4][8];
        #pragma unroll
        for (int r = 0; r < 4; r++)
            #pragma unroll
            for (int j = 0; j < 4; j++)
                up2(acc[r][j], v[r][2 * j], v[r][2 * j + 1]);
        #pragma unroll
        for (int r = 0; r < 4; r++)
            #pragma unroll
            for (int o = 0; o < 8; o++)
                v[r][o] = tanhhw(v[r][o]);
        #pragma unroll
        for (int o = 0; o < 8; o++) {
            int c = colbase + g * NO + 8 * h + o;
            __half2 p0 = __floats2half2_rn(v[0][o], v[1][o]);
            __half2 p1 = __floats2half2_rn(v[2][o], v[3][o]);
            uint2 st;
            st.x = reinterpret_cast<unsigned&>(p0);
            st.y = reinterpret_cast<unsigned&>(p1);
            *qp(tile, c, s) = st;
        }
    }
}

__global__ void __launch_bounds__(NTHR, 2)
model_kernel(const float* __restrict__ x,
             const float* __restrict__ W1, const float* __restrict__ b1,
             const float* __restrict__ W2, const float* __restrict__ b2,
             const float* __restrict__ W3, const float* __restrict__ b3,
             const float* __restrict__ Wo, const float* __restrict__ bo,
             const int* __restrict__ idx1, const int* __restrict__ idx2,
             const int* __restrict__ idx3, const int* __restrict__ idxo,
             float* __restrict__ out)
{
    extern __shared__ uint2 tile[];  // [ACCC][4 slots] fp16, slot-hash swizzle
    const int t = threadIdx.x;
    const int rowbase = blockIdx.x * RT;

    // ---- Stage x tile (16 rows x 512 cols) fp32->fp16 into SMEM ----
    {
        const float* xb = x + (size_t)rowbase * INC;
        #pragma unroll
        for (int k = 0; k < 8; k++) {
            int i  = t + k * NTHR;       // 0..2047
            int c  = i & 511;
            int qd = i >> 9;             // slot 0..3
            float r0 = __ldg(&xb[(4 * qd + 0) * INC + c]);
            float r1 = __ldg(&xb[(4 * qd + 1) * INC + c]);
            float r2 = __ldg(&xb[(4 * qd + 2) * INC + c]);
            float r3 = __ldg(&xb[(4 * qd + 3) * INC + c]);
            __half2 p0 = __floats2half2_rn(r0, r1);
            __half2 p1 = __floats2half2_rn(r2, r3);
            uint2 st;
            st.x = reinterpret_cast<unsigned&>(p0);
            st.y = reinterpret_cast<unsigned&>(p1);
            *qp(tile, c, qd) = st;
        }
    }
    __syncthreads();

    const int g = t >> 2;   // group 0..63
    const int s = t & 3;    // row-quad 0..3

    glayer(tile, g, s, W1, b1, idx1, 512);
    __syncthreads();
    glayer(tile, g, s, W2, b2, idx2, 1536);
    __syncthreads();
    glayer(tile, g, s, W3, b3, idx3, 2560);
    __syncthreads();

    // ---- Output layer: 4 groups x 48 f x 16 o, linear, fp32 out ----
    {
        int ot = t & 15;
        int og = (t >> 4) & 3;
        int so = t >> 6;                 // row-quad 0..3
        float bias = __ldg(&bo[og * 16 + ot]);
        u64 bd = pk2(bias, bias);
        u64 h01 = bd, h23 = bd;
        const int* gi = idxo + og * 48;
        const float* w = Wo + og * 48 * 16 + ot;
        #pragma unroll
        for (int f = 0; f < 48; f++) {
            int c = __ldg(&gi[f]);
            uint2 a = *qp(tile, c, so);
            float2 r01 = h2f(a.x), r23 = h2f(a.y);
            float wf = __ldg(&w[f * 16]);
            u64 wd = pk2(wf, wf);
            h01 = fma2(pk2(r01.x, r01.y), wd, h01);
            h23 = fma2(pk2(r23.x, r23.y), wd, h23);
        }
        float hv[4];
        up2(h01, hv[0], hv[1]);
        up2(h23, hv[2], hv[3]);
        float* ob = out + (size_t)(rowbase + 4 * so) * 64 + og * 16 + ot;
        ob[0]   = hv[0];
        ob[64]  = hv[1];
        ob[128] = hv[2];
        ob[192] = hv[3];
    }
}

extern "C" void kernel_launch(void* const* d_in, const int* in_sizes, int n_in,
                              void* d_out, int out_size)
{
    const float* x   = (const float*)d_in[0];
    const float* W1  = (const float*)d_in[1];
    const float* b1  = (const float*)d_in[2];
    const float* W2  = (const float*)d_in[3];
    const float* b2  = (const float*)d_in[4];
    const float* W3  = (const float*)d_in[5];
    const float* b3  = (const float*)d_in[6];
    const float* Wo  = (const float*)d_in[7];
    const float* bo  = (const float*)d_in[8];
    const int*   i1  = (const int*)d_in[9];
    const int*   i2  = (const int*)d_in[10];
    const int*   i3  = (const int*)d_in[11];
    const int*   io  = (const int*)d_in[12];
    float*       out = (float*)d_out;

    cudaFuncSetAttribute(model_kernel,
                         cudaFuncAttributeMaxDynamicSharedMemorySize, TILE_BYTES);
    model_kernel<<<NROWS / RT, NTHR, TILE_BYTES>>>(
        x, W1, b1, W2, b2, W3, b3, Wo, bo, i1, i2, i3, io, out);
}